// round 13
// baseline (speedup 1.0000x reference)
#include <cuda_runtime.h>
#include <cuda_fp16.h>

#define N_USERS  100000
#define N_ITEMS  200000
#define N_NODES  300000
#define NNZ      9600000
#define DIM      64
#define TOTAL_F  (N_NODES * DIM)          // 19,200,000
#define TOTAL_V4 (TOTAL_F / 4)            // 4,800,000
#define USER_V4  (N_USERS * DIM / 4)      // 1,600,000

#define SCAN_BLK 1024
#define N_SCAN_BLKS ((N_NODES + SCAN_BLK - 1) / SCAN_BLK)   // 293

// Scratch (alloc-free rule: __device__ globals)
__device__ __half g_A[(size_t)TOTAL_F];   // fp16 ping  (38.4 MB)
__device__ __half g_B[(size_t)TOTAL_F];   // fp16 pong  (38.4 MB)
__device__ int2   g_edge[(size_t)NNZ];    // CSR (col, val_bits)  (76.8 MB)
__device__ int    g_cnt[N_NODES];         // histogram, then scatter cursor
__device__ int    g_ptr[N_NODES + 1];     // CSR row pointers
__device__ int    g_bsum[512];            // per-block scan sums

// ---------------------------------------------------------------------------
__device__ __forceinline__ unsigned long long pack_half4(float4 v) {
    __half2 p0 = __floats2half2_rn(v.x, v.y);
    __half2 p1 = __floats2half2_rn(v.z, v.w);
    unsigned long long r;
    asm("mov.b64 %0, {%1, %2};" : "=l"(r)
        : "r"(*(unsigned*)&p0), "r"(*(unsigned*)&p1));
    return r;
}

// ---------------------------------------------------------------------------
// init: A = half(e0); out = 0.25*e0; cnt = 0
// ---------------------------------------------------------------------------
__global__ void init_kernel(const float4* __restrict__ user,
                            const float4* __restrict__ item,
                            float4* __restrict__ out) {
    int i = blockIdx.x * blockDim.x + threadIdx.x;
    if (i < N_NODES) g_cnt[i] = 0;
    if (i >= TOTAL_V4) return;
    float4 v = (i < USER_V4) ? __ldg(&user[i]) : __ldg(&item[i - USER_V4]);
    out[i] = make_float4(0.25f*v.x, 0.25f*v.y, 0.25f*v.z, 0.25f*v.w);
    reinterpret_cast<unsigned long long*>(g_A)[i] = pack_half4(v);
}

// ---------------------------------------------------------------------------
// histogram of destination rows
// ---------------------------------------------------------------------------
__global__ void hist_kernel(const int4* __restrict__ rows4) {
    int t = blockIdx.x * blockDim.x + threadIdx.x;     // < NNZ/4
    int4 r = __ldcs(&rows4[t]);
    atomicAdd(&g_cnt[r.x], 1);
    atomicAdd(&g_cnt[r.y], 1);
    atomicAdd(&g_cnt[r.z], 1);
    atomicAdd(&g_cnt[r.w], 1);
}

// ---------------------------------------------------------------------------
// 3-stage exclusive scan of g_cnt -> g_ptr
// ---------------------------------------------------------------------------
__global__ void scan1_kernel() {
    __shared__ int s[SCAN_BLK];
    int tid = threadIdx.x;
    int i = blockIdx.x * SCAN_BLK + tid;
    int v = (i < N_NODES) ? g_cnt[i] : 0;
    s[tid] = v;
    __syncthreads();
    for (int off = 1; off < SCAN_BLK; off <<= 1) {
        int t = (tid >= off) ? s[tid - off] : 0;
        __syncthreads();
        s[tid] += t;
        __syncthreads();
    }
    if (i < N_NODES) g_ptr[i] = s[tid] - v;            // exclusive (block-local)
    if (tid == SCAN_BLK - 1) g_bsum[blockIdx.x] = s[tid];
}

__global__ void scan2_kernel() {
    __shared__ int s[512];
    int tid = threadIdx.x;
    int v = (tid < N_SCAN_BLKS) ? g_bsum[tid] : 0;
    s[tid] = v;
    __syncthreads();
    for (int off = 1; off < 512; off <<= 1) {
        int t = (tid >= off) ? s[tid - off] : 0;
        __syncthreads();
        s[tid] += t;
        __syncthreads();
    }
    g_bsum[tid] = s[tid] - v;                          // exclusive block offsets
}

__global__ void scan3_kernel() {
    int tid = threadIdx.x;
    int i = blockIdx.x * SCAN_BLK + tid;
    if (i < N_NODES) {
        int p = g_ptr[i] + g_bsum[blockIdx.x];
        g_ptr[i] = p;
        g_cnt[i] = p;                                  // scatter cursor
    }
    if (i == 0) g_ptr[N_NODES] = NNZ;
}

// ---------------------------------------------------------------------------
// scatter edges into CSR order: g_edge[cursor[row]++] = (col, val)
// ---------------------------------------------------------------------------
__global__ void scatter_kernel(const int4* __restrict__ rows4,
                               const int4* __restrict__ cols4,
                               const float4* __restrict__ vals4) {
    int t = blockIdx.x * blockDim.x + threadIdx.x;     // < NNZ/4
    int4   r = __ldcs(&rows4[t]);
    int4   c = __ldcs(&cols4[t]);
    float4 v = __ldcs(&vals4[t]);
    int idx;
    idx = atomicAdd(&g_cnt[r.x], 1); g_edge[idx] = make_int2(c.x, __float_as_int(v.x));
    idx = atomicAdd(&g_cnt[r.y], 1); g_edge[idx] = make_int2(c.y, __float_as_int(v.y));
    idx = atomicAdd(&g_cnt[r.z], 1); g_edge[idx] = make_int2(c.z, __float_as_int(v.z));
    idx = atomicAdd(&g_cnt[r.w], 1); g_edge[idx] = make_int2(c.w, __float_as_int(v.w));
}

// ---------------------------------------------------------------------------
// CSR SpMM, one warp per node, fp32 accumulation, NO atomics:
//   y[n] = sum_e val_e * x[col_e]   (x,y fp16 rows of 128B)
//   out[n] += 0.25 * y[n]           (fused epilogue, fp32)
// Lane l owns bytes [4l, 4l+4) of the row (2 halves).
// ---------------------------------------------------------------------------
__global__ void __launch_bounds__(256)
csr_spmm_kernel(const __half* __restrict__ x,
                __half*       __restrict__ y,
                float*        __restrict__ out) {
    __shared__ int2 sh[8][32];
    int wl = threadIdx.x >> 5;
    int l  = threadIdx.x & 31;
    int n  = blockIdx.x * 8 + wl;                      // node id, < 300000 exactly

    int b = __ldg(&g_ptr[n]);
    int e = __ldg(&g_ptr[n + 1]);

    unsigned long long pol;
    asm("createpolicy.fractional.L2::evict_last.b64 %0, 1.0;" : "=l"(pol));

    const char* xb = reinterpret_cast<const char*>(x);
    float accx = 0.f, accy = 0.f;

    for (int i0 = b; i0 < e; i0 += 32) {
        int k = e - i0; if (k > 32) k = 32;
        if (l < k) sh[wl][l] = __ldcs(&g_edge[i0 + l]);
        __syncwarp();
        #pragma unroll 4
        for (int j = 0; j < k; j++) {
            int2 ed = sh[wl][j];
            float v = __int_as_float(ed.y);
            unsigned q;
            asm volatile("ld.global.nc.L2::cache_hint.b32 %0, [%1], %2;"
                         : "=r"(q)
                         : "l"(xb + (size_t)ed.x * 128 + l * 4), "l"(pol));
            float2 xv = __half22float2(*(__half2*)&q);
            accx += v * xv.x;
            accy += v * xv.y;
        }
        __syncwarp();
    }

    // y[n] (fp16, for next layer's gather)
    reinterpret_cast<__half2*>(y)[(size_t)n * 32 + l] = __floats2half2_rn(accx, accy);

    // fused: out[n] += 0.25 * y_row (fp32)
    float2* op = reinterpret_cast<float2*>(out) + (size_t)n * 32 + l;
    float2 o = *op;
    o.x += 0.25f * accx;
    o.y += 0.25f * accy;
    *op = o;
}

// ---------------------------------------------------------------------------
extern "C" void kernel_launch(void* const* d_in, const int* in_sizes, int n_in,
                              void* d_out, int out_size) {
    const int4*   rows4 = (const int4*)  d_in[0];
    const int4*   cols4 = (const int4*)  d_in[1];
    const float4* vals4 = (const float4*)d_in[2];
    const float4* user  = (const float4*)d_in[3];
    const float4* item  = (const float4*)d_in[4];
    float* out = (float*)d_out;

    __half *A, *B;
    cudaGetSymbolAddress((void**)&A, g_A);
    cudaGetSymbolAddress((void**)&B, g_B);

    const int STREAM_GRID = (TOTAL_V4 + 255) / 256;    // 18750
    const int EDGE_GRID   = (NNZ / 4) / 256;           // 9375, exact
    const int SPMM_GRID   = N_NODES / 8;               // 37500, exact

    // e0 setup + histogram zero
    init_kernel<<<STREAM_GRID, 256>>>(user, item, (float4*)out);

    // Build CSR (reused by all 3 layers)
    hist_kernel<<<EDGE_GRID, 256>>>(rows4);
    scan1_kernel<<<N_SCAN_BLKS, SCAN_BLK>>>();
    scan2_kernel<<<1, 512>>>();
    scan3_kernel<<<N_SCAN_BLKS, SCAN_BLK>>>();
    scatter_kernel<<<EDGE_GRID, 256>>>(rows4, cols4, vals4);

    // 3 atomic-free layers, each with fused  out += 0.25*layer
    csr_spmm_kernel<<<SPMM_GRID, 256>>>(A, B, out);    // e1 = S e0
    csr_spmm_kernel<<<SPMM_GRID, 256>>>(B, A, out);    // e2 = S e1
    csr_spmm_kernel<<<SPMM_GRID, 256>>>(A, B, out);    // e3 = S e2
}